// round 10
// baseline (speedup 1.0000x reference)
#include <cuda_runtime.h>
#include <math.h>

#define TT 512
#define DD 512
#define NBATCH 2
#define VV 256
#define MMEM 256
#define BT 1024
#define D3 1536
#define FUSE_BLOCKS 128
#define UNITS 4
#define GRU_THREADS 384
#define CANARY 0x7FC00001u

// ---------------- static device scratch ----------------
__device__ float g_table[VV * D3];
__device__ float g_ps[BT * DD];
__device__ float g_qkv[BT * D3];
__device__ float g_S[NBATCH * TT * TT];
__device__ float g_den[BT];
__device__ float g_attn[BT * MMEM];
__device__ float g_comb[BT * 2048];
__device__ float g_tpre[BT * DD];
__device__ float g_gatepre[BT * DD];
__device__ float g_qh[BT * DD];
__device__ float g_sw[VV * DD];
// full per-step hidden-state histories (no reuse -> no barrier needed)
__device__ float g_hfh[(TT + 1) * NBATCH * DD];
__device__ float g_hsh[(TT + 1) * NBATCH * DD];

// ---------------- block reductions ----------------
__device__ __forceinline__ float block_red_sum(float v, float* sb) {
    __syncthreads();
    int lane = threadIdx.x & 31, w = threadIdx.x >> 5;
    #pragma unroll
    for (int o = 16; o; o >>= 1) v += __shfl_xor_sync(0xffffffffu, v, o);
    if (lane == 0) sb[w] = v;
    __syncthreads();
    float r = (lane < (int)(blockDim.x >> 5)) ? sb[lane] : 0.f;
    #pragma unroll
    for (int o = 16; o; o >>= 1) r += __shfl_xor_sync(0xffffffffu, r, o);
    return r;
}

__device__ __forceinline__ float block_red_max(float v, float* sb) {
    __syncthreads();
    int lane = threadIdx.x & 31, w = threadIdx.x >> 5;
    #pragma unroll
    for (int o = 16; o; o >>= 1) v = fmaxf(v, __shfl_xor_sync(0xffffffffu, v, o));
    if (lane == 0) sb[w] = v;
    __syncthreads();
    float r = (lane < (int)(blockDim.x >> 5)) ? sb[lane] : -3.4e38f;
    #pragma unroll
    for (int o = 16; o; o >>= 1) r = fmaxf(r, __shfl_xor_sync(0xffffffffu, r, o));
    return r;
}

// ---------------- poison kernel: fill histories with canary ----------------
__global__ void poison_kernel() {
    const uint4 c = make_uint4(CANARY, CANARY, CANARY, CANARY);
    const int n = (TT + 1) * NBATCH * DD / 4;
    for (int i = blockIdx.x * blockDim.x + threadIdx.x; i < n; i += gridDim.x * blockDim.x) {
        ((uint4*)g_hfh)[i] = c;
        ((uint4*)g_hsh)[i] = c;
    }
}

// ---------------- fast activations ----------------
__device__ __forceinline__ float sigf(float x) {
    return __fdividef(1.f, 1.f + __expf(-x));
}
__device__ __forceinline__ float tanhf_fast(float x) {
    float ax = fabsf(x);
    float t = __expf(-2.f * ax);
    float r = __fdividef(1.f - t, 1.f + t);
    return copysignf(r, x);
}

#define FMA2(d, a, b, c) \
    asm("fma.rn.f32x2 %0, %1, %2, %3;" : "=l"(d) : "l"(a), "l"(b), "l"(c))

__device__ __forceinline__ ulonglong2 ldvol2(const void* p) {
    ulonglong2 v;
    asm volatile("ld.volatile.global.v2.u64 {%0,%1}, [%2];"
                 : "=l"(v.x), "=l"(v.y) : "l"(p));
    return v;
}
__device__ __forceinline__ bool ok64(unsigned long long v) {
    return ((unsigned)v != CANARY) & ((unsigned)(v >> 32) != CANARY);
}
__device__ __forceinline__ void st_rel(float* p, float v) {
    asm volatile("st.release.gpu.global.f32 [%0], %1;" :: "l"(p), "f"(v) : "memory");
}

// ---------------- fused pipelined GRU, barrier-free dataflow ----------------
// 128 blocks x 384 threads. Warp = (trio, unit): trio 0 = fast_whh dots,
// trio 1 = slow_wih dots (reads same hf_hist[t]), trio 2 = slow_whh dots.
// Weights in registers; h histories polled directly (canary-poisoned).
__global__ void __launch_bounds__(GRU_THREADS) fused_gru_kernel(
    const float* __restrict__ fast_whh, const float* __restrict__ fast_bhh,
    const float* __restrict__ slow_wih, const float* __restrict__ slow_bih,
    const float* __restrict__ slow_whh, const float* __restrict__ slow_bhh,
    const float* __restrict__ gi_table, const int* __restrict__ toks,
    const float* __restrict__ hf0, const float* __restrict__ hs0,
    float* __restrict__ comb, float* __restrict__ ps,
    float* __restrict__ hfT, float* __restrict__ hsT)
{
    __shared__ float sg[2][3][3][NBATCH][UNITS];   // [phase][trio][gate][batch][unit]
    const int tid = threadIdx.x;
    const int w = tid >> 5, lane = tid & 31;
    const int il = w & 3, tr = w >> 2;
    const int ibase = blockIdx.x * UNITS;
    const int i = ibase + il;

    const float* Wsrc = (tr == 0) ? fast_whh : ((tr == 1) ? slow_wih : slow_whh);
    ulonglong2 wreg[3][4];
    #pragma unroll
    for (int g = 0; g < 3; g++)
        #pragma unroll
        for (int j = 0; j < 4; j++)
            wreg[g][j] = *(const ulonglong2*)&Wsrc[(size_t)(g * DD + i) * DD + lane * 4 + j * 128];

    const int cb = lane >> 2, cil = lane & 3;
    const int ci = ibase + cil;
    float fb_r = 0.f, fb_z = 0.f, fb_n = 0.f;
    float sbi_r = 0.f, sbi_z = 0.f, sbi_n = 0.f, sbh_r = 0.f, sbh_z = 0.f, sbh_n = 0.f;
    float hf_prev = 0.f, hs_prev = 0.f;   // cell state lives in registers
    if (w == 0 && lane < 8) {
        fb_r = fast_bhh[ci]; fb_z = fast_bhh[DD + ci]; fb_n = fast_bhh[2 * DD + ci];
        hf_prev = hf0[cb * DD + ci];
        st_rel(&g_hfh[cb * DD + ci], hf_prev);          // hist[0]
    }
    if (w == 1 && lane < 8) {
        sbi_r = slow_bih[ci]; sbi_z = slow_bih[DD + ci]; sbi_n = slow_bih[2 * DD + ci];
        sbh_r = slow_bhh[ci]; sbh_z = slow_bhh[DD + ci]; sbh_n = slow_bhh[2 * DD + ci];
        hs_prev = hs0[cb * DD + ci];
        st_rel(&g_hsh[cb * DD + ci], hs_prev);          // hist[0]
    }

    for (int t = 0; t <= TT; t++) {
        const int ph = t & 1;

        // fast-cell input-gate prefetch (independent of the h dependency)
        float gr = 0.f, gz = 0.f, gn = 0.f;
        if (w == 0 && lane < 8 && t < TT) {
            const int row = cb * TT + t;
            const float* gi = gi_table + (size_t)__ldg(&toks[row]) * D3;
            gr = __ldg(gi + ci); gz = __ldg(gi + DD + ci); gn = __ldg(gi + 2 * DD + ci);
        }

        // poll this trio's input vector until all words are real data
        const float* base = (tr == 2)
            ? &g_hsh[((t > 0) ? t - 1 : 0) * (NBATCH * DD)]
            : &g_hfh[(size_t)t * (NBATCH * DD)];
        ulonglong2 xv[NBATCH][4];
        bool ok;
        do {
            #pragma unroll
            for (int b = 0; b < NBATCH; b++)
                #pragma unroll
                for (int j = 0; j < 4; j++)
                    xv[b][j] = ldvol2(base + b * DD + lane * 4 + j * 128);
            ok = true;
            #pragma unroll
            for (int b = 0; b < NBATCH; b++)
                #pragma unroll
                for (int j = 0; j < 4; j++)
                    ok &= ok64(xv[b][j].x) & ok64(xv[b][j].y);
        } while (!__all_sync(0xffffffffu, ok));

        // 6 dot products via packed f32x2 FFMA
        unsigned long long acc2[3][NBATCH];
        #pragma unroll
        for (int g = 0; g < 3; g++)
            #pragma unroll
            for (int b = 0; b < NBATCH; b++) acc2[g][b] = 0ull;
        #pragma unroll
        for (int j = 0; j < 4; j++)
            #pragma unroll
            for (int g = 0; g < 3; g++)
                #pragma unroll
                for (int b = 0; b < NBATCH; b++) {
                    FMA2(acc2[g][b], wreg[g][j].x, xv[b][j].x, acc2[g][b]);
                    FMA2(acc2[g][b], wreg[g][j].y, xv[b][j].y, acc2[g][b]);
                }

        float a[3][NBATCH];
        #pragma unroll
        for (int g = 0; g < 3; g++)
            #pragma unroll
            for (int b = 0; b < NBATCH; b++) {
                float lo, hi;
                asm("mov.b64 {%0, %1}, %2;" : "=f"(lo), "=f"(hi) : "l"(acc2[g][b]));
                a[g][b] = lo + hi;
            }
        #pragma unroll
        for (int o = 16; o; o >>= 1)
            #pragma unroll
            for (int g = 0; g < 3; g++)
                #pragma unroll
                for (int b = 0; b < NBATCH; b++)
                    a[g][b] += __shfl_xor_sync(0xffffffffu, a[g][b], o);

        if (lane == 0) {
            #pragma unroll
            for (int g = 0; g < 3; g++)
                #pragma unroll
                for (int b = 0; b < NBATCH; b++)
                    sg[ph][tr][g][b][il] = a[g][b];
        }
        __syncthreads();

        if (w == 0 && lane < 8 && t < TT) {         // fast GRU step t
            const int row = cb * TT + t;
            float r = sigf(gr + sg[ph][0][0][cb][cil] + fb_r);
            float z = sigf(gz + sg[ph][0][1][cb][cil] + fb_z);
            float n = tanhf_fast(gn + r * (sg[ph][0][2][cb][cil] + fb_n));
            float hnew = (1.f - z) * n + z * hf_prev;
            hf_prev = hnew;
            st_rel(&g_hfh[(size_t)(t + 1) * (NBATCH * DD) + cb * DD + ci], hnew);
            comb[(size_t)row * 2048 + ci] = hnew;
            if (t == TT - 1) hfT[cb * DD + ci] = hnew;
        }
        if (w == 1 && lane < 8 && t >= 1) {         // slow GRU step t-1
            const int ts = t - 1, row = cb * TT + ts;
            float r = sigf(sg[ph][1][0][cb][cil] + sbi_r + sg[ph][2][0][cb][cil] + sbh_r);
            float z = sigf(sg[ph][1][1][cb][cil] + sbi_z + sg[ph][2][1][cb][cil] + sbh_z);
            float n = tanhf_fast(sg[ph][1][2][cb][cil] + sbi_n + r * (sg[ph][2][2][cb][cil] + sbh_n));
            float hnew = (1.f - z) * n + z * hs_prev;
            hs_prev = hnew;
            st_rel(&g_hsh[(size_t)t * (NBATCH * DD) + cb * DD + ci], hnew);
            ps[(size_t)row * DD + ci] = hnew;
            if (ts == TT - 1) hsT[cb * DD + ci] = hnew;
        }
    }
}

// ---------------- GEMM: 128x64 tile, 256 thr, 8x4/thread, f32x2 FMA ----------------
// TB=true : Bm stored [N,K]  (C = A @ Bm^T);  TB=false: Bm stored [K,N]
template <bool TB, bool CAUSAL>
__global__ void __launch_bounds__(256) gemm_kernel(
    const float* __restrict__ A, const float* __restrict__ Bm,
    const float* __restrict__ bias, float* __restrict__ C,
    int M, int N, int K, int lda, int ldb, int ldc,
    long long sA, long long sB, long long sC, float scale)
{
    __shared__ __align__(16) float As[2][16][132];
    __shared__ __align__(16) float Bs[2][16][68];
    const int z = blockIdx.z;
    A += (size_t)z * sA; Bm += (size_t)z * sB; C += (size_t)z * sC;
    const int m0 = blockIdx.y * 128, n0 = blockIdx.x * 64;
    const int tid = threadIdx.x;
    const int ar = tid >> 2, ac = (tid & 3) << 2;
    const int bk = tid >> 4, bn = (tid & 15) << 2;
    const int ty = tid >> 4, tx = tid & 15;

    float4 a0 = *(const float4*)(A + (size_t)(m0 + ar) * lda + ac);
    float4 a1 = *(const float4*)(A + (size_t)(m0 + ar + 64) * lda + ac);
    float4 bv;
    if (TB) bv = *(const float4*)(Bm + (size_t)(n0 + ar) * ldb + ac);
    else    bv = *(const float4*)(Bm + (size_t)bk * ldb + n0 + bn);

    {
        As[0][ac + 0][ar] = a0.x; As[0][ac + 1][ar] = a0.y;
        As[0][ac + 2][ar] = a0.z; As[0][ac + 3][ar] = a0.w;
        As[0][ac + 0][ar + 64] = a1.x; As[0][ac + 1][ar + 64] = a1.y;
        As[0][ac + 2][ar + 64] = a1.z; As[0][ac + 3][ar + 64] = a1.w;
        if (TB) {
            Bs[0][ac + 0][ar] = bv.x; Bs[0][ac + 1][ar] = bv.y;
            Bs[0][ac + 2][ar] = bv.z; Bs[0][ac + 3][ar] = bv.w;
        } else {
            *(float4*)&Bs[0][bk][bn] = bv;
        }
    }
    __syncthreads();

    unsigned long long acc[4][4];
    #pragma unroll
    for (int p2 = 0; p2 < 4; p2++)
        #pragma unroll
        for (int jj = 0; jj < 4; jj++) acc[p2][jj] = 0ull;

    const int P = K >> 4;
    int buf = 0;
    for (int p = 0; p < P; p++) {
        if (p + 1 < P) {
            const int k0n = (p + 1) << 4;
            a0 = *(const float4*)(A + (size_t)(m0 + ar) * lda + k0n + ac);
            a1 = *(const float4*)(A + (size_t)(m0 + ar + 64) * lda + k0n + ac);
            if (TB) bv = *(const float4*)(Bm + (size_t)(n0 + ar) * ldb + k0n + ac);
            else    bv = *(const float4*)(Bm + (size_t)(k0n + bk) * ldb + n0 + bn);
        }
        #pragma unroll
        for (int k = 0; k < 16; k++) {
            ulonglong2 alo = *(const ulonglong2*)&As[buf][k][ty << 3];
            ulonglong2 ahi = *(const ulonglong2*)&As[buf][k][(ty << 3) + 4];
            float4 b4 = *(const float4*)&Bs[buf][k][tx << 2];
            unsigned long long bd[4];
            asm("mov.b64 %0, {%1, %1};" : "=l"(bd[0]) : "f"(b4.x));
            asm("mov.b64 %0, {%1, %1};" : "=l"(bd[1]) : "f"(b4.y));
            asm("mov.b64 %0, {%1, %1};" : "=l"(bd[2]) : "f"(b4.z));
            asm("mov.b64 %0, {%1, %1};" : "=l"(bd[3]) : "f"(b4.w));
            #pragma unroll
            for (int jj = 0; jj < 4; jj++) {
                FMA2(acc[0][jj], alo.x, bd[jj], acc[0][jj]);
                FMA2(acc[1][jj], alo.y, bd[jj], acc[1][jj]);
                FMA2(acc[2][jj], ahi.x, bd[jj], acc[2][jj]);
                FMA2(acc[3][jj], ahi.y, bd[jj], acc[3][jj]);
            }
        }
        if (p + 1 < P) {
            const int nb = buf ^ 1;
            As[nb][ac + 0][ar] = a0.x; As[nb][ac + 1][ar] = a0.y;
            As[nb][ac + 2][ar] = a0.z; As[nb][ac + 3][ar] = a0.w;
            As[nb][ac + 0][ar + 64] = a1.x; As[nb][ac + 1][ar + 64] = a1.y;
            As[nb][ac + 2][ar + 64] = a1.z; As[nb][ac + 3][ar + 64] = a1.w;
            if (TB) {
                Bs[nb][ac + 0][ar] = bv.x; Bs[nb][ac + 1][ar] = bv.y;
                Bs[nb][ac + 2][ar] = bv.z; Bs[nb][ac + 3][ar] = bv.w;
            } else {
                *(float4*)&Bs[nb][bk][bn] = bv;
            }
            __syncthreads();
            buf = nb;
        }
    }

    const int nn = n0 + (tx << 2);
    float4 bvec;
    if (bias) bvec = *(const float4*)&bias[nn];
    #pragma unroll
    for (int p2 = 0; p2 < 4; p2++) {
        float rlo[4], rhi[4];
        #pragma unroll
        for (int jj = 0; jj < 4; jj++) {
            float lo, hi;
            asm("mov.b64 {%0, %1}, %2;" : "=f"(lo), "=f"(hi) : "l"(acc[p2][jj]));
            rlo[jj] = lo; rhi[jj] = hi;
        }
        #pragma unroll
        for (int half = 0; half < 2; half++) {
            const int mm = m0 + (ty << 3) + (p2 << 1) + half;
            float* rr = half ? rhi : rlo;
            float4 cv;
            cv.x = rr[0] * scale; cv.y = rr[1] * scale;
            cv.z = rr[2] * scale; cv.w = rr[3] * scale;
            if (bias) { cv.x += bvec.x; cv.y += bvec.y; cv.z += bvec.z; cv.w += bvec.w; }
            if (CAUSAL) {
                if (nn + 0 > mm) cv.x = 0.f;
                if (nn + 1 > mm) cv.y = 0.f;
                if (nn + 2 > mm) cv.z = 0.f;
                if (nn + 3 > mm) cv.w = 0.f;
            }
            *(float4*)(C + (size_t)mm * ldc + nn) = cv;
        }
    }
}

// ---------------- small kernels ----------------
__global__ void elu_qk_kernel() {
    int idx = blockIdx.x * blockDim.x + threadIdx.x;
    if (idx >= BT * 1024) return;
    int row = idx >> 10, c = idx & 1023;
    float* p = &g_qkv[(size_t)row * D3 + c];
    float x = *p;
    *p = x > 0.f ? x + 1.f : __expf(x);
}

__global__ void den_kernel() {
    __shared__ float sb[32];
    int row = blockIdx.x;
    float s = 0.f;
    for (int c = threadIdx.x; c < TT; c += 256) s += g_S[(size_t)row * TT + c];
    s = block_red_sum(s, sb);
    if (threadIdx.x == 0) g_den[row] = s;
}

__global__ void div_kernel() {
    int idx = blockIdx.x * blockDim.x + threadIdx.x;
    if (idx >= BT * DD) return;
    int row = idx >> 9, j = idx & 511;
    g_comb[(size_t)row * 2048 + 1024 + j] /= (g_den[row] + 1e-6f);
}

__global__ void softmax_kernel() {
    __shared__ float sb[32];
    int row = blockIdx.x;
    float x = g_attn[(size_t)row * MMEM + threadIdx.x];
    float m = block_red_max(x, sb);
    float e = __expf(x - m);
    float s = block_red_sum(e, sb);
    g_attn[(size_t)row * MMEM + threadIdx.x] = e / s;
}

__device__ __forceinline__ float tanh_bulk(float x) {
    float ax = fabsf(x);
    float t = __expf(-2.f * ax);
    float r = __fdividef(1.f - t, 1.f + t);
    return copysignf(r, x);
}

// mode 0: out = tanh(LN(in));  mode 1: out = LN(tanh(in))
__global__ void ln_kernel(const float* __restrict__ in, const float* __restrict__ gg,
                          const float* __restrict__ bb, float* __restrict__ out,
                          int ldo, int mode)
{
    __shared__ float sb[32];
    int row = blockIdx.x, tid = threadIdx.x;
    float x0 = in[(size_t)row * DD + tid];
    float x1 = in[(size_t)row * DD + 256 + tid];
    if (mode == 1) { x0 = tanh_bulk(x0); x1 = tanh_bulk(x1); }
    float s  = block_red_sum(x0 + x1, sb);
    float sq = block_red_sum(x0 * x0 + x1 * x1, sb);
    float mean = s * (1.f / 512.f);
    float var  = sq * (1.f / 512.f) - mean * mean;
    float rstd = rsqrtf(var + 1e-5f);
    float y0 = (x0 - mean) * rstd * gg[tid] + bb[tid];
    float y1 = (x1 - mean) * rstd * gg[256 + tid] + bb[256 + tid];
    if (mode == 0) { y0 = tanh_bulk(y0); y1 = tanh_bulk(y1); }
    out[(size_t)row * ldo + tid] = y0;
    out[(size_t)row * ldo + 256 + tid] = y1;
}

__global__ void rownorm_kernel(const float* __restrict__ src) {
    __shared__ float sb[32];
    int row = blockIdx.x, tid = threadIdx.x;
    float x0 = src[(size_t)row * DD + tid];
    float x1 = src[(size_t)row * DD + 256 + tid];
    float ss = block_red_sum(x0 * x0 + x1 * x1, sb);
    float inv = 1.f / fmaxf(sqrtf(ss), 1e-12f);
    g_sw[(size_t)row * DD + tid] = x0 * inv;
    g_sw[(size_t)row * DD + 256 + tid] = x1 * inv;
}

// ---------------- host ----------------
static inline void gemm(const float* A, const float* B, const float* bias, float* C,
                        int M, int N, int K, int lda, int ldb, int ldc,
                        float scale, int batch, long long sA, long long sB, long long sC,
                        bool tb, bool causal)
{
    dim3 grid(N / 64, M / 128, batch);
    if (tb) {
        if (causal)
            gemm_kernel<true, true><<<grid, 256>>>(A, B, bias, C, M, N, K, lda, ldb, ldc, sA, sB, sC, scale);
        else
            gemm_kernel<true, false><<<grid, 256>>>(A, B, bias, C, M, N, K, lda, ldb, ldc, sA, sB, sC, scale);
    } else {
        gemm_kernel<false, false><<<grid, 256>>>(A, B, bias, C, M, N, K, lda, ldb, ldc, sA, sB, sC, scale);
    }
}

extern "C" void kernel_launch(void* const* d_in, const int* in_sizes, int n_in,
                              void* d_out, int out_size)
{
    (void)in_sizes; (void)n_in; (void)out_size;
    const int*   x        = (const int*)d_in[0];
    const float* h_f      = (const float*)d_in[1];
    const float* h_s      = (const float*)d_in[2];
    const float* soma_w   = (const float*)d_in[3];
    const float* fast_wih = (const float*)d_in[4];
    const float* fast_whh = (const float*)d_in[5];
    const float* fast_bih = (const float*)d_in[6];
    const float* fast_bhh = (const float*)d_in[7];
    const float* slow_wih = (const float*)d_in[8];
    const float* slow_whh = (const float*)d_in[9];
    const float* slow_bih = (const float*)d_in[10];
    const float* slow_bhh = (const float*)d_in[11];
    const float* qkv_w    = (const float*)d_in[12];
    const float* qkv_b    = (const float*)d_in[13];
    const float* gate_w   = (const float*)d_in[14];
    const float* gate_b   = (const float*)d_in[15];
    const float* gate_g   = (const float*)d_in[16];
    const float* gate_bb  = (const float*)d_in[17];
    const float* mem_bank = (const float*)d_in[18];
    const float* hip_qw   = (const float*)d_in[19];
    const float* hip_qb   = (const float*)d_in[20];
    const float* axon_w   = (const float*)d_in[21];
    const float* axon_b   = (const float*)d_in[22];
    const float* norm_g   = (const float*)d_in[23];
    const float* norm_b   = (const float*)d_in[24];

    float* out = (float*)d_out;
    float* out_logits  = out;            // [B,T,V]
    float* out_thought = out + 262144;   // [B,T,D]
    float* out_hf      = out + 786432;   // [1,B,D]
    float* out_hs      = out + 787456;   // [1,B,D]

    float *p_table, *p_ps, *p_qkv, *p_S, *p_attn, *p_comb,
          *p_tpre, *p_gatepre, *p_qh, *p_sw;
    cudaGetSymbolAddress((void**)&p_table,   g_table);
    cudaGetSymbolAddress((void**)&p_ps,      g_ps);
    cudaGetSymbolAddress((void**)&p_qkv,     g_qkv);
    cudaGetSymbolAddress((void**)&p_S,       g_S);
    cudaGetSymbolAddress((void**)&p_attn,    g_attn);
    cudaGetSymbolAddress((void**)&p_comb,    g_comb);
    cudaGetSymbolAddress((void**)&p_tpre,    g_tpre);
    cudaGetSymbolAddress((void**)&p_gatepre, g_gatepre);
    cudaGetSymbolAddress((void**)&p_qh,      g_qh);
    cudaGetSymbolAddress((void**)&p_sw,      g_sw);

    // normalized embedding rows for logits
    rownorm_kernel<<<VV, 256>>>(soma_w);

    // fast-GRU input-gate token table: [V,3D] = soma_w @ fast_wih^T + fast_bih
    gemm(soma_w, fast_wih, fast_bih, p_table, 256, 1536, 512, 512, 512, 1536,
         1.f, 1, 0, 0, 0, true, false);

    // poison the state histories (must precede the GRU each launch/replay)
    poison_kernel<<<512, 256>>>();

    // fused pipelined GRUs (barrier-free dataflow) -> comb[:,0:512], p_s, hf1, hs1
    fused_gru_kernel<<<FUSE_BLOCKS, GRU_THREADS>>>(
        fast_whh, fast_bhh, slow_wih, slow_bih, slow_whh, slow_bhh,
        p_table, x, h_f, h_s, p_comb, p_ps, out_hf, out_hs);

    // projections from p_s
    gemm(p_ps, qkv_w,  qkv_b,  p_qkv,     1024, 1536, 512, 512, 512, 1536, 1.f, 1, 0, 0, 0, true, false);
    gemm(p_ps, gate_w, gate_b, p_gatepre, 1024,  512, 512, 512, 512,  512, 1.f, 1, 0, 0, 0, true, false);
    gemm(p_ps, hip_qw, hip_qb, p_qh,      1024,  512, 512, 512, 512,  512, 1.f, 1, 0, 0, 0, true, false);

    // q,k <- elu+1
    elu_qk_kernel<<<(BT * 1024) / 256, 256>>>();

    // linear attention == causal attention: S = q k^T (masked), per batch
    gemm(p_qkv, p_qkv + 512, nullptr, p_S, 512, 512, 512, 1536, 1536, 512,
         1.f, 2, 512LL * 1536, 512LL * 1536, 512LL * 512, true, true);
    den_kernel<<<BT, 256>>>();
    // num = S @ v -> combined[:, 1024:1536]
    gemm(p_S, p_qkv + 1024, nullptr, p_comb + 1024, 512, 512, 512, 512, 1536, 2048,
         1.f, 2, 512LL * 512, 512LL * 1536, 512LL * 2048, false, false);
    div_kernel<<<(BT * DD) / 256, 256>>>();

    // intent = tanh(LN(gatepre)) -> combined[:, 512:1024]
    ln_kernel<<<BT, 256>>>(p_gatepre, gate_g, gate_bb, p_comb + 512, 2048, 0);

    // hippocampus: attn = softmax(qh @ mem^T / sqrt(D)); episodes = attn @ mem
    gemm(p_qh, mem_bank, nullptr, p_attn, 1024, 256, 512, 512, 512, 256,
         0.044194173824159216f, 1, 0, 0, 0, true, false);
    softmax_kernel<<<BT, 256>>>();
    gemm(p_attn, mem_bank, nullptr, p_comb + 1536, 1024, 512, 256, 256, 512, 2048,
         1.f, 1, 0, 0, 0, false, false);

    // thought = LN(tanh(combined @ axon_w^T + axon_b))
    gemm(p_comb, axon_w, axon_b, p_tpre, 1024, 512, 2048, 2048, 2048, 512,
         1.f, 1, 0, 0, 0, true, false);
    ln_kernel<<<BT, 256>>>(p_tpre, norm_g, norm_b, out_thought, 512, 1);

    // logits = (thought @ sw^T) * 16
    gemm(out_thought, p_sw, nullptr, out_logits, 1024, 256, 512, 512, 512, 256,
         16.f, 1, 0, 0, 0, true, false);
}

// round 11
// speedup vs baseline: 2.2379x; 2.2379x over previous
#include <cuda_runtime.h>
#include <math.h>

#define TT 512
#define DD 512
#define NBATCH 2
#define VV 256
#define MMEM 256
#define BT 1024
#define D3 1536
#define FUSE_BLOCKS 128
#define UNITS 4
#define GRU_THREADS 384
#define NBDD (NBATCH * DD)

// ---------------- static device scratch ----------------
__device__ float g_table[VV * D3];
__device__ float g_ps[BT * DD];
__device__ float g_qkv[BT * D3];
__device__ float g_S[NBATCH * TT * TT];
__device__ float g_den[BT];
__device__ float g_attn[BT * MMEM];
__device__ float g_comb[BT * 2048];
__device__ float g_tpre[BT * DD];
__device__ float g_gatepre[BT * DD];
__device__ float g_qh[BT * DD];
__device__ float g_sw[VV * DD];
// write-once per-step hidden-state histories
__device__ float g_hfh[(TT + 1) * NBDD];   // hfh[t] = fast state after step t-1
__device__ float g_hsh[(TT + 1) * NBDD];   // hsh[t] = slow state after step t-1
__device__ unsigned g_bar;

// ---------------- block reductions ----------------
__device__ __forceinline__ float block_red_sum(float v, float* sb) {
    __syncthreads();
    int lane = threadIdx.x & 31, w = threadIdx.x >> 5;
    #pragma unroll
    for (int o = 16; o; o >>= 1) v += __shfl_xor_sync(0xffffffffu, v, o);
    if (lane == 0) sb[w] = v;
    __syncthreads();
    float r = (lane < (int)(blockDim.x >> 5)) ? sb[lane] : 0.f;
    #pragma unroll
    for (int o = 16; o; o >>= 1) r += __shfl_xor_sync(0xffffffffu, r, o);
    return r;
}

__device__ __forceinline__ float block_red_max(float v, float* sb) {
    __syncthreads();
    int lane = threadIdx.x & 31, w = threadIdx.x >> 5;
    #pragma unroll
    for (int o = 16; o; o >>= 1) v = fmaxf(v, __shfl_xor_sync(0xffffffffu, v, o));
    if (lane == 0) sb[w] = v;
    __syncthreads();
    float r = (lane < (int)(blockDim.x >> 5)) ? sb[lane] : -3.4e38f;
    #pragma unroll
    for (int o = 16; o; o >>= 1) r = fmaxf(r, __shfl_xor_sync(0xffffffffu, r, o));
    return r;
}

// ---------------- global barrier: single counter, single poller (R7/R9 proven) ----------------
__device__ __forceinline__ void grid_bar(unsigned no) {
    __syncthreads();
    if (threadIdx.x == 0) {
        asm volatile("red.release.gpu.global.add.u32 [%0], 1;" :: "l"(&g_bar) : "memory");
        unsigned target = no * FUSE_BLOCKS;
        unsigned v;
        do {
            asm volatile("ld.acquire.gpu.u32 %0, [%1];" : "=r"(v) : "l"(&g_bar) : "memory");
        } while (v < target);
    }
    __syncthreads();
}

__global__ void reset_bar_kernel() { g_bar = 0u; }

// ---------------- fast activations ----------------
__device__ __forceinline__ float sigf(float x) {
    return __fdividef(1.f, 1.f + __expf(-x));
}
__device__ __forceinline__ float tanhf_fast(float x) {
    float ax = fabsf(x);
    float t = __expf(-2.f * ax);
    float r = __fdividef(1.f - t, 1.f + t);
    return copysignf(r, x);
}

#define FMA2(d, a, b, c) \
    asm("fma.rn.f32x2 %0, %1, %2, %3;" : "=l"(d) : "l"(a), "l"(b), "l"(c))

// ---------------- fused pipelined GRU: R9 barrier + write-once histories + L1 dedup ----------------
// 128 blocks x 384 threads. Warp = (trio, unit): trio 0 = fast_whh dots (reads hfh[t]),
// trio 1 = slow_wih dots (reads the SAME hfh[t]), trio 2 = slow_whh dots (reads hsh[t-1]).
// Weights in registers; h histories written once, read with plain L1-cached loads.
__global__ void __launch_bounds__(GRU_THREADS) fused_gru_kernel(
    const float* __restrict__ fast_whh, const float* __restrict__ fast_bhh,
    const float* __restrict__ slow_wih, const float* __restrict__ slow_bih,
    const float* __restrict__ slow_whh, const float* __restrict__ slow_bhh,
    const float* __restrict__ gi_table, const int* __restrict__ toks,
    const float* __restrict__ hf0, const float* __restrict__ hs0,
    float* __restrict__ comb, float* __restrict__ ps,
    float* __restrict__ hfT, float* __restrict__ hsT)
{
    __shared__ float sg[3][3][NBATCH][UNITS];   // [trio][gate][batch][unit]
    const int tid = threadIdx.x;
    const int w = tid >> 5, lane = tid & 31;
    const int il = w & 3, tr = w >> 2;
    const int ibase = blockIdx.x * UNITS;
    const int i = ibase + il;

    const float* Wsrc = (tr == 0) ? fast_whh : ((tr == 1) ? slow_wih : slow_whh);
    ulonglong2 wreg[3][4];
    #pragma unroll
    for (int g = 0; g < 3; g++)
        #pragma unroll
        for (int j = 0; j < 4; j++)
            wreg[g][j] = *(const ulonglong2*)&Wsrc[(size_t)(g * DD + i) * DD + lane * 4 + j * 128];

    const int cb = lane >> 2, cil = lane & 3;
    const int ci = ibase + cil;
    float fb_r = 0.f, fb_z = 0.f, fb_n = 0.f;
    float sbi_r = 0.f, sbi_z = 0.f, sbi_n = 0.f, sbh_r = 0.f, sbh_z = 0.f, sbh_n = 0.f;
    float hf_prev = 0.f, hs_prev = 0.f;   // cell state lives in registers
    if (w == 0 && lane < 8) {
        fb_r = fast_bhh[ci]; fb_z = fast_bhh[DD + ci]; fb_n = fast_bhh[2 * DD + ci];
        hf_prev = hf0[cb * DD + ci];
        g_hfh[cb * DD + ci] = hf_prev;                  // hist[0]
    }
    if (w == 1 && lane < 8) {
        sbi_r = slow_bih[ci]; sbi_z = slow_bih[DD + ci]; sbi_n = slow_bih[2 * DD + ci];
        sbh_r = slow_bhh[ci]; sbh_z = slow_bhh[DD + ci]; sbh_n = slow_bhh[2 * DD + ci];
        hs_prev = hs0[cb * DD + ci];
        g_hsh[cb * DD + ci] = hs_prev;                  // hist[0]
    }
    grid_bar(1u);

    for (int t = 0; t <= TT; t++) {
        // fast-cell input-gate prefetch (independent of the h dependency)
        float gr = 0.f, gz = 0.f, gn = 0.f;
        if (w == 0 && lane < 8 && t < TT) {
            const int row = cb * TT + t;
            const float* gi = gi_table + (size_t)__ldg(&toks[row]) * D3;
            gr = __ldg(gi + ci); gz = __ldg(gi + DD + ci); gn = __ldg(gi + 2 * DD + ci);
        }

        // this trio's input vector (plain loads -> L1 dedup across the 8/4 warps)
        const float* base = (tr == 2)
            ? &g_hsh[(size_t)((t > 0) ? t - 1 : 0) * NBDD]
            : &g_hfh[(size_t)t * NBDD];
        ulonglong2 xv[NBATCH][4];
        #pragma unroll
        for (int b = 0; b < NBATCH; b++)
            #pragma unroll
            for (int j = 0; j < 4; j++)
                xv[b][j] = *(const ulonglong2*)(base + b * DD + lane * 4 + j * 128);

        // 6 dot products via packed f32x2 FFMA
        unsigned long long acc2[3][NBATCH];
        #pragma unroll
        for (int g = 0; g < 3; g++)
            #pragma unroll
            for (int b = 0; b < NBATCH; b++) acc2[g][b] = 0ull;
        #pragma unroll
        for (int j = 0; j < 4; j++)
            #pragma unroll
            for (int g = 0; g < 3; g++)
                #pragma unroll
                for (int b = 0; b < NBATCH; b++) {
                    FMA2(acc2[g][b], wreg[g][j].x, xv[b][j].x, acc2[g][b]);
                    FMA2(acc2[g][b], wreg[g][j].y, xv[b][j].y, acc2[g][b]);
                }

        float a[3][NBATCH];
        #pragma unroll
        for (int g = 0; g < 3; g++)
            #pragma unroll
            for (int b = 0; b < NBATCH; b++) {
                float lo, hi;
                asm("mov.b64 {%0, %1}, %2;" : "=f"(lo), "=f"(hi) : "l"(acc2[g][b]));
                a[g][b] = lo + hi;
            }
        #pragma unroll
        for (int o = 16; o; o >>= 1)
            #pragma unroll
            for (int g = 0; g < 3; g++)
                #pragma unroll
                for (int b = 0; b < NBATCH; b++)
                    a[g][b] += __shfl_xor_sync(0xffffffffu, a[g][b], o);

        if (lane == 0) {
            #pragma unroll
            for (int g = 0; g < 3; g++)
                #pragma unroll
                for (int b = 0; b < NBATCH; b++)
                    sg[tr][g][b][il] = a[g][b];
        }
        __syncthreads();

        if (w == 0 && lane < 8 && t < TT) {         // fast GRU step t
            const int row = cb * TT + t;
            float r = sigf(gr + sg[0][0][cb][cil] + fb_r);
            float z = sigf(gz + sg[0][1][cb][cil] + fb_z);
            float n = tanhf_fast(gn + r * (sg[0][2][cb][cil] + fb_n));
            float hnew = (1.f - z) * n + z * hf_prev;
            hf_prev = hnew;
            g_hfh[(size_t)(t + 1) * NBDD + cb * DD + ci] = hnew;
            comb[(size_t)row * 2048 + ci] = hnew;
            if (t == TT - 1) hfT[cb * DD + ci] = hnew;
        }
        if (w == 1 && lane < 8 && t >= 1) {         // slow GRU step t-1
            const int ts = t - 1, row = cb * TT + ts;
            float r = sigf(sg[1][0][cb][cil] + sbi_r + sg[2][0][cb][cil] + sbh_r);
            float z = sigf(sg[1][1][cb][cil] + sbi_z + sg[2][1][cb][cil] + sbh_z);
            float n = tanhf_fast(sg[1][2][cb][cil] + sbi_n + r * (sg[2][2][cb][cil] + sbh_n));
            float hnew = (1.f - z) * n + z * hs_prev;
            hs_prev = hnew;
            g_hsh[(size_t)t * NBDD + cb * DD + ci] = hnew;
            ps[(size_t)row * DD + ci] = hnew;
            if (ts == TT - 1) hsT[cb * DD + ci] = hnew;
        }
        if (t < TT) grid_bar((unsigned)(t + 2));
    }
}

// ---------------- GEMM: 128x64 tile, 256 thr, 8x4/thread, f32x2 FMA ----------------
// TB=true : Bm stored [N,K]  (C = A @ Bm^T);  TB=false: Bm stored [K,N]
template <bool TB, bool CAUSAL>
__global__ void __launch_bounds__(256) gemm_kernel(
    const float* __restrict__ A, const float* __restrict__ Bm,
    const float* __restrict__ bias, float* __restrict__ C,
    int M, int N, int K, int lda, int ldb, int ldc,
    long long sA, long long sB, long long sC, float scale)
{
    __shared__ __align__(16) float As[2][16][132];
    __shared__ __align__(16) float Bs[2][16][68];
    const int z = blockIdx.z;
    A += (size_t)z * sA; Bm += (size_t)z * sB; C += (size_t)z * sC;
    const int m0 = blockIdx.y * 128, n0 = blockIdx.x * 64;
    const int tid = threadIdx.x;
    const int ar = tid >> 2, ac = (tid & 3) << 2;
    const int bk = tid >> 4, bn = (tid & 15) << 2;
    const int ty = tid >> 4, tx = tid & 15;

    float4 a0 = *(const float4*)(A + (size_t)(m0 + ar) * lda + ac);
    float4 a1 = *(const float4*)(A + (size_t)(m0 + ar + 64) * lda + ac);
    float4 bv;
    if (TB) bv = *(const float4*)(Bm + (size_t)(n0 + ar) * ldb + ac);
    else    bv = *(const float4*)(Bm + (size_t)bk * ldb + n0 + bn);

    {
        As[0][ac + 0][ar] = a0.x; As[0][ac + 1][ar] = a0.y;
        As[0][ac + 2][ar] = a0.z; As[0][ac + 3][ar] = a0.w;
        As[0][ac + 0][ar + 64] = a1.x; As[0][ac + 1][ar + 64] = a1.y;
        As[0][ac + 2][ar + 64] = a1.z; As[0][ac + 3][ar + 64] = a1.w;
        if (TB) {
            Bs[0][ac + 0][ar] = bv.x; Bs[0][ac + 1][ar] = bv.y;
            Bs[0][ac + 2][ar] = bv.z; Bs[0][ac + 3][ar] = bv.w;
        } else {
            *(float4*)&Bs[0][bk][bn] = bv;
        }
    }
    __syncthreads();

    unsigned long long acc[4][4];
    #pragma unroll
    for (int p2 = 0; p2 < 4; p2++)
        #pragma unroll
        for (int jj = 0; jj < 4; jj++) acc[p2][jj] = 0ull;

    const int P = K >> 4;
    int buf = 0;
    for (int p = 0; p < P; p++) {
        if (p + 1 < P) {
            const int k0n = (p + 1) << 4;
            a0 = *(const float4*)(A + (size_t)(m0 + ar) * lda + k0n + ac);
            a1 = *(const float4*)(A + (size_t)(m0 + ar + 64) * lda + k0n + ac);
            if (TB) bv = *(const float4*)(Bm + (size_t)(n0 + ar) * ldb + k0n + ac);
            else    bv = *(const float4*)(Bm + (size_t)(k0n + bk) * ldb + n0 + bn);
        }
        #pragma unroll
        for (int k = 0; k < 16; k++) {
            ulonglong2 alo = *(const ulonglong2*)&As[buf][k][ty << 3];
            ulonglong2 ahi = *(const ulonglong2*)&As[buf][k][(ty << 3) + 4];
            float4 b4 = *(const float4*)&Bs[buf][k][tx << 2];
            unsigned long long bd[4];
            asm("mov.b64 %0, {%1, %1};" : "=l"(bd[0]) : "f"(b4.x));
            asm("mov.b64 %0, {%1, %1};" : "=l"(bd[1]) : "f"(b4.y));
            asm("mov.b64 %0, {%1, %1};" : "=l"(bd[2]) : "f"(b4.z));
            asm("mov.b64 %0, {%1, %1};" : "=l"(bd[3]) : "f"(b4.w));
            #pragma unroll
            for (int jj = 0; jj < 4; jj++) {
                FMA2(acc[0][jj], alo.x, bd[jj], acc[0][jj]);
                FMA2(acc[1][jj], alo.y, bd[jj], acc[1][jj]);
                FMA2(acc[2][jj], ahi.x, bd[jj], acc[2][jj]);
                FMA2(acc[3][jj], ahi.y, bd[jj], acc[3][jj]);
            }
        }
        if (p + 1 < P) {
            const int nb = buf ^ 1;
            As[nb][ac + 0][ar] = a0.x; As[nb][ac + 1][ar] = a0.y;
            As[nb][ac + 2][ar] = a0.z; As[nb][ac + 3][ar] = a0.w;
            As[nb][ac + 0][ar + 64] = a1.x; As[nb][ac + 1][ar + 64] = a1.y;
            As[nb][ac + 2][ar + 64] = a1.z; As[nb][ac + 3][ar + 64] = a1.w;
            if (TB) {
                Bs[nb][ac + 0][ar] = bv.x; Bs[nb][ac + 1][ar] = bv.y;
                Bs[nb][ac + 2][ar] = bv.z; Bs[nb][ac + 3][ar] = bv.w;
            } else {
                *(float4*)&Bs[nb][bk][bn] = bv;
            }
            __syncthreads();
            buf = nb;
        }
    }

    const int nn = n0 + (tx << 2);
    float4 bvec;
    if (bias) bvec = *(const float4*)&bias[nn];
    #pragma unroll
    for (int p2 = 0; p2 < 4; p2++) {
        float rlo[4], rhi[4];
        #pragma unroll
        for (int jj = 0; jj < 4; jj++) {
            float lo, hi;
            asm("mov.b64 {%0, %1}, %2;" : "=f"(lo), "=f"(hi) : "l"(acc[p2][jj]));
            rlo[jj] = lo; rhi[jj] = hi;
        }
        #pragma unroll
        for (int half = 0; half < 2; half++) {
            const int mm = m0 + (ty << 3) + (p2 << 1) + half;
            float* rr = half ? rhi : rlo;
            float4 cv;
            cv.x = rr[0] * scale; cv.y = rr[1] * scale;
            cv.z = rr[2] * scale; cv.w = rr[3] * scale;
            if (bias) { cv.x += bvec.x; cv.y += bvec.y; cv.z += bvec.z; cv.w += bvec.w; }
            if (CAUSAL) {
                if (nn + 0 > mm) cv.x = 0.f;
                if (nn + 1 > mm) cv.y = 0.f;
                if (nn + 2 > mm) cv.z = 0.f;
                if (nn + 3 > mm) cv.w = 0.f;
            }
            *(float4*)(C + (size_t)mm * ldc + nn) = cv;
        }
    }
}

// ---------------- small kernels ----------------
__global__ void elu_qk_kernel() {
    int idx = blockIdx.x * blockDim.x + threadIdx.x;
    if (idx >= BT * 1024) return;
    int row = idx >> 10, c = idx & 1023;
    float* p = &g_qkv[(size_t)row * D3 + c];
    float x = *p;
    *p = x > 0.f ? x + 1.f : __expf(x);
}

__global__ void den_kernel() {
    __shared__ float sb[32];
    int row = blockIdx.x;
    float s = 0.f;
    for (int c = threadIdx.x; c < TT; c += 256) s += g_S[(size_t)row * TT + c];
    s = block_red_sum(s, sb);
    if (threadIdx.x == 0) g_den[row] = s;
}

__global__ void div_kernel() {
    int idx = blockIdx.x * blockDim.x + threadIdx.x;
    if (idx >= BT * DD) return;
    int row = idx >> 9, j = idx & 511;
    g_comb[(size_t)row * 2048 + 1024 + j] /= (g_den[row] + 1e-6f);
}

__global__ void softmax_kernel() {
    __shared__ float sb[32];
    int row = blockIdx.x;
    float x = g_attn[(size_t)row * MMEM + threadIdx.x];
    float m = block_red_max(x, sb);
    float e = __expf(x - m);
    float s = block_red_sum(e, sb);
    g_attn[(size_t)row * MMEM + threadIdx.x] = e / s;
}

__device__ __forceinline__ float tanh_bulk(float x) {
    float ax = fabsf(x);
    float t = __expf(-2.f * ax);
    float r = __fdividef(1.f - t, 1.f + t);
    return copysignf(r, x);
}

// mode 0: out = tanh(LN(in));  mode 1: out = LN(tanh(in))
__global__ void ln_kernel(const float* __restrict__ in, const float* __restrict__ gg,
                          const float* __restrict__ bb, float* __restrict__ out,
                          int ldo, int mode)
{
    __shared__ float sb[32];
    int row = blockIdx.x, tid = threadIdx.x;
    float x0 = in[(size_t)row * DD + tid];
    float x1 = in[(size_t)row * DD + 256 + tid];
    if (mode == 1) { x0 = tanh_bulk(x0); x1 = tanh_bulk(x1); }
    float s  = block_red_sum(x0 + x1, sb);
    float sq = block_red_sum(x0 * x0 + x1 * x1, sb);
    float mean = s * (1.f / 512.f);
    float var  = sq * (1.f / 512.f) - mean * mean;
    float rstd = rsqrtf(var + 1e-5f);
    float y0 = (x0 - mean) * rstd * gg[tid] + bb[tid];
    float y1 = (x1 - mean) * rstd * gg[256 + tid] + bb[256 + tid];
    if (mode == 0) { y0 = tanh_bulk(y0); y1 = tanh_bulk(y1); }
    out[(size_t)row * ldo + tid] = y0;
    out[(size_t)row * ldo + 256 + tid] = y1;
}

__global__ void rownorm_kernel(const float* __restrict__ src) {
    __shared__ float sb[32];
    int row = blockIdx.x, tid = threadIdx.x;
    float x0 = src[(size_t)row * DD + tid];
    float x1 = src[(size_t)row * DD + 256 + tid];
    float ss = block_red_sum(x0 * x0 + x1 * x1, sb);
    float inv = 1.f / fmaxf(sqrtf(ss), 1e-12f);
    g_sw[(size_t)row * DD + tid] = x0 * inv;
    g_sw[(size_t)row * DD + 256 + tid] = x1 * inv;
}

// ---------------- host ----------------
static inline void gemm(const float* A, const float* B, const float* bias, float* C,
                        int M, int N, int K, int lda, int ldb, int ldc,
                        float scale, int batch, long long sA, long long sB, long long sC,
                        bool tb, bool causal)
{
    dim3 grid(N / 64, M / 128, batch);
    if (tb) {
        if (causal)
            gemm_kernel<true, true><<<grid, 256>>>(A, B, bias, C, M, N, K, lda, ldb, ldc, sA, sB, sC, scale);
        else
            gemm_kernel<true, false><<<grid, 256>>>(A, B, bias, C, M, N, K, lda, ldb, ldc, sA, sB, sC, scale);
    } else {
        gemm_kernel<false, false><<<grid, 256>>>(A, B, bias, C, M, N, K, lda, ldb, ldc, sA, sB, sC, scale);
    }
}

extern "C" void kernel_launch(void* const* d_in, const int* in_sizes, int n_in,
                              void* d_out, int out_size)
{
    (void)in_sizes; (void)n_in; (void)out_size;
    const int*   x        = (const int*)d_in[0];
    const float* h_f      = (const float*)d_in[1];
    const float* h_s      = (const float*)d_in[2];
    const float* soma_w   = (const float*)d_in[3];
    const float* fast_wih = (const float*)d_in[4];
    const float* fast_whh = (const float*)d_in[5];
    const float* fast_bih = (const float*)d_in[6];
    const float* fast_bhh = (const float*)d_in[7];
    const float* slow_wih = (const float*)d_in[8];
    const float* slow_whh = (const float*)d_in[9];
    const float* slow_bih = (const float*)d_in[10];
    const float* slow_bhh = (const float*)d_in[11];
    const float* qkv_w    = (const float*)d_in[12];
    const float* qkv_b    = (const float*)d_in[13];
    const float* gate_w   = (const float*)d_in[14];
    const float* gate_b   = (const float*)d_in[15];
    const float* gate_g   = (const float*)d_in[16];
    const float* gate_bb  = (const float*)d_in[17];
    const float* mem_bank = (const float*)d_in[18];
    const float* hip_qw   = (const float*)d_in[19];
    const float* hip_qb   = (const float*)d_in[20];
    const float* axon_w   = (const float*)d_in[21];
    const float* axon_b   = (const float*)d_in[22];
    const float* norm_g   = (const float*)d_in[23];
    const float* norm_b   = (const float*)d_in[24];

    float* out = (float*)d_out;
    float* out_logits  = out;            // [B,T,V]
    float* out_thought = out + 262144;   // [B,T,D]
    float* out_hf      = out + 786432;   // [1,B,D]
    float* out_hs      = out + 787456;   // [1,B,D]

    float *p_table, *p_ps, *p_qkv, *p_S, *p_attn, *p_comb,
          *p_tpre, *p_gatepre, *p_qh, *p_sw;
    cudaGetSymbolAddress((void**)&p_table,   g_table);
    cudaGetSymbolAddress((void**)&p_ps,      g_ps);
    cudaGetSymbolAddress((void**)&p_qkv,     g_qkv);
    cudaGetSymbolAddress((void**)&p_S,       g_S);
    cudaGetSymbolAddress((void**)&p_attn,    g_attn);
    cudaGetSymbolAddress((void**)&p_comb,    g_comb);
    cudaGetSymbolAddress((void**)&p_tpre,    g_tpre);
    cudaGetSymbolAddress((void**)&p_gatepre, g_gatepre);
    cudaGetSymbolAddress((void**)&p_qh,      g_qh);
    cudaGetSymbolAddress((void**)&p_sw,      g_sw);

    // normalized embedding rows for logits
    rownorm_kernel<<<VV, 256>>>(soma_w);

    // fast-GRU input-gate token table: [V,3D] = soma_w @ fast_wih^T + fast_bih
    gemm(soma_w, fast_wih, fast_bih, p_table, 256, 1536, 512, 512, 512, 1536,
         1.f, 1, 0, 0, 0, true, false);

    // reset counter BEFORE the GRU (keeps fused_gru in the ncu window)
    reset_bar_kernel<<<1, 1>>>();

    // fused pipelined GRUs -> comb[:,0:512], p_s, hf1, hs1
    fused_gru_kernel<<<FUSE_BLOCKS, GRU_THREADS>>>(
        fast_whh, fast_bhh, slow_wih, slow_bih, slow_whh, slow_bhh,
        p_table, x, h_f, h_s, p_comb, p_ps, out_hf, out_hs);

    // projections from p_s
    gemm(p_ps, qkv_w,  qkv_b,  p_qkv,     1024, 1536, 512, 512, 512, 1536, 1.f, 1, 0, 0, 0, true, false);
    gemm(p_ps, gate_w, gate_b, p_gatepre, 1024,  512, 512, 512, 512,  512, 1.f, 1, 0, 0, 0, true, false);
    gemm(p_ps, hip_qw, hip_qb, p_qh,      1024,  512, 512, 512, 512,  512, 1.f, 1, 0, 0, 0, true, false);

    // q,k <- elu+1
    elu_qk_kernel<<<(BT * 1024) / 256, 256>>>();

    // linear attention == causal attention: S = q k^T (masked), per batch
    gemm(p_qkv, p_qkv + 512, nullptr, p_S, 512, 512, 512, 1536, 1536, 512,
         1.f, 2, 512LL * 1536, 512LL * 1536, 512LL * 512, true, true);
    den_kernel<<<BT, 256>>>();
    // num = S @ v -> combined[:, 1024:1536]
    gemm(p_S, p_qkv + 1024, nullptr, p_comb + 1024, 512, 512, 512, 512, 1536, 2048,
         1.f, 2, 512LL * 512, 512LL * 1536, 512LL * 2048, false, false);
    div_kernel<<<(BT * DD) / 256, 256>>>();

    // intent = tanh(LN(gatepre)) -> combined[:, 512:1024]
    ln_kernel<<<BT, 256>>>(p_gatepre, gate_g, gate_bb, p_comb + 512, 2048, 0);

    // hippocampus: attn = softmax(qh @ mem^T / sqrt(D)); episodes = attn @ mem
    gemm(p_qh, mem_bank, nullptr, p_attn, 1024, 256, 512, 512, 512, 256,
         0.044194173824159216f, 1, 0, 0, 0, true, false);
    softmax_kernel<<<BT, 256>>>();
    gemm(p_attn, mem_bank, nullptr, p_comb + 1536, 1024, 512, 256, 256, 512, 2048,
         1.f, 1, 0, 0, 0, false, false);

    // thought = LN(tanh(combined @ axon_w^T + axon_b))
    gemm(p_comb, axon_w, axon_b, p_tpre, 1024, 512, 2048, 2048, 2048, 512,
         1.f, 1, 0, 0, 0, true, false);
    ln_kernel<<<BT, 256>>>(p_tpre, norm_g, norm_b, out_thought, 512, 1);

    // logits = (thought @ sw^T) * 16
    gemm(out_thought, p_sw, nullptr, out_logits, 1024, 256, 512, 512, 512, 256,
         16.f, 1, 0, 0, 0, true, false);
}

// round 12
// speedup vs baseline: 2.4066x; 1.0754x over previous
#include <cuda_runtime.h>
#include <math.h>

#define TT 512
#define DD 512
#define NBATCH 2
#define VV 256
#define MMEM 256
#define BT 1024
#define D3 1536
#define FUSE_BLOCKS 128
#define UNITS 4
#define GRU_THREADS 384

// ---------------- static device scratch ----------------
__device__ float g_table[VV * D3];
__device__ float g_pf[BT * DD];
__device__ float g_ps[BT * DD];
__device__ float g_qkv[BT * D3];
__device__ float g_S[NBATCH * TT * TT];
__device__ float g_attn[BT * MMEM];
__device__ float g_comb[BT * 2048];
__device__ float g_tpre[BT * DD];
__device__ float g_gatepre[BT * DD];
__device__ float g_qh[BT * DD];
__device__ float g_sw[VV * DD];
__device__ float g_hf3[3][NBATCH * DD];
__device__ float g_hs3[3][NBATCH * DD];
__device__ unsigned g_bar;

// ---------------- block reductions ----------------
__device__ __forceinline__ float block_red_sum(float v, float* sb) {
    __syncthreads();
    int lane = threadIdx.x & 31, w = threadIdx.x >> 5;
    #pragma unroll
    for (int o = 16; o; o >>= 1) v += __shfl_xor_sync(0xffffffffu, v, o);
    if (lane == 0) sb[w] = v;
    __syncthreads();
    float r = (lane < (int)(blockDim.x >> 5)) ? sb[lane] : 0.f;
    #pragma unroll
    for (int o = 16; o; o >>= 1) r += __shfl_xor_sync(0xffffffffu, r, o);
    return r;
}

__device__ __forceinline__ float block_red_max(float v, float* sb) {
    __syncthreads();
    int lane = threadIdx.x & 31, w = threadIdx.x >> 5;
    #pragma unroll
    for (int o = 16; o; o >>= 1) v = fmaxf(v, __shfl_xor_sync(0xffffffffu, v, o));
    if (lane == 0) sb[w] = v;
    __syncthreads();
    float r = (lane < (int)(blockDim.x >> 5)) ? sb[lane] : -3.4e38f;
    #pragma unroll
    for (int o = 16; o; o >>= 1) r = fmaxf(r, __shfl_xor_sync(0xffffffffu, r, o));
    return r;
}

// ---------------- global barrier: single counter, single poller (proven best) ----------------
__device__ __forceinline__ void grid_bar(unsigned no) {
    __syncthreads();
    if (threadIdx.x == 0) {
        asm volatile("red.release.gpu.global.add.u32 [%0], 1;" :: "l"(&g_bar) : "memory");
        unsigned target = no * FUSE_BLOCKS;
        unsigned v;
        do {
            asm volatile("ld.acquire.gpu.u32 %0, [%1];" : "=r"(v) : "l"(&g_bar) : "memory");
        } while (v < target);
    }
    __syncthreads();
}

__global__ void reset_bar_kernel() { g_bar = 0u; }

// ---------------- fast activations (MUFU-based, ~1e-6 rel err) ----------------
__device__ __forceinline__ float sigf(float x) {
    return __fdividef(1.f, 1.f + __expf(-x));
}
__device__ __forceinline__ float tanhf_fast(float x) {
    float ax = fabsf(x);
    float t = __expf(-2.f * ax);
    float r = __fdividef(1.f - t, 1.f + t);
    return copysignf(r, x);
}

#define FMA2(d, a, b, c) \
    asm("fma.rn.f32x2 %0, %1, %2, %3;" : "=l"(d) : "l"(a), "l"(b), "l"(c))

// ---------------- fused pipelined GRU (R9 proven: 1713us config) ----------------
__global__ void __launch_bounds__(GRU_THREADS) fused_gru_kernel(
    const float* __restrict__ fast_whh, const float* __restrict__ fast_bhh,
    const float* __restrict__ slow_wih, const float* __restrict__ slow_bih,
    const float* __restrict__ slow_whh, const float* __restrict__ slow_bhh,
    const float* __restrict__ gi_table, const int* __restrict__ toks,
    const float* __restrict__ hf0, const float* __restrict__ hs0,
    float* __restrict__ pf, float* __restrict__ comb, float* __restrict__ ps,
    float* __restrict__ hfT, float* __restrict__ hsT)
{
    __shared__ float sg[3][3][NBATCH][UNITS];   // [trio][gate][batch][unit]
    const int tid = threadIdx.x;
    const int w = tid >> 5, lane = tid & 31;
    const int il = w & 3, tr = w >> 2;
    const int ibase = blockIdx.x * UNITS;
    const int i = ibase + il;

    const float* Wsrc = (tr == 0) ? fast_whh : ((tr == 1) ? slow_wih : slow_whh);
    ulonglong2 wreg[3][4];
    #pragma unroll
    for (int g = 0; g < 3; g++)
        #pragma unroll
        for (int j = 0; j < 4; j++)
            wreg[g][j] = *(const ulonglong2*)&Wsrc[(size_t)(g * DD + i) * DD + lane * 4 + j * 128];

    const int cb = lane >> 2, cil = lane & 3;
    const int ci = ibase + cil;
    float fb_r = 0.f, fb_z = 0.f, fb_n = 0.f;
    float sbi_r = 0.f, sbi_z = 0.f, sbi_n = 0.f, sbh_r = 0.f, sbh_z = 0.f, sbh_n = 0.f;
    if (w == 0 && lane < 8) {
        fb_r = fast_bhh[ci]; fb_z = fast_bhh[DD + ci]; fb_n = fast_bhh[2 * DD + ci];
        g_hf3[0][cb * DD + ci] = hf0[cb * DD + ci];
    }
    if (w == 1 && lane < 8) {
        sbi_r = slow_bih[ci]; sbi_z = slow_bih[DD + ci]; sbi_n = slow_bih[2 * DD + ci];
        sbh_r = slow_bhh[ci]; sbh_z = slow_bhh[DD + ci]; sbh_n = slow_bhh[2 * DD + ci];
        g_hs3[0][cb * DD + ci] = hs0[cb * DD + ci];
    }
    grid_bar(1u);

    for (int t = 0; t <= TT; t++) {
        const int cur = t % 3, nxt = (t + 1) % 3;
        const int cur_s = (t + 2) % 3, nxt_s = t % 3;

        float gr = 0.f, gz = 0.f, gn = 0.f, hprev = 0.f;
        if (w == 0 && lane < 8 && t < TT) {
            const int row = cb * TT + t;
            const float* gi = gi_table + (size_t)__ldg(&toks[row]) * D3;
            gr = __ldg(gi + ci); gz = __ldg(gi + DD + ci); gn = __ldg(gi + 2 * DD + ci);
            hprev = __ldcg(&g_hf3[cur][cb * DD + ci]);
        }
        if (w == 1 && lane < 8 && t >= 1)
            hprev = __ldcg(&g_hs3[cur_s][cb * DD + ci]);

        ulonglong2 xv[NBATCH][4];
        if (tr == 0) {
            #pragma unroll
            for (int b = 0; b < NBATCH; b++)
                #pragma unroll
                for (int j = 0; j < 4; j++)
                    xv[b][j] = __ldcg((const ulonglong2*)&g_hf3[cur][b * DD + lane * 4 + j * 128]);
        } else if (tr == 1) {
            const int tm1 = (t > 0) ? t - 1 : 0;
            #pragma unroll
            for (int b = 0; b < NBATCH; b++) {
                const float* pfb = pf + (size_t)(b * TT + tm1) * DD;
                #pragma unroll
                for (int j = 0; j < 4; j++)
                    xv[b][j] = __ldcg((const ulonglong2*)(pfb + lane * 4 + j * 128));
            }
        } else {
            #pragma unroll
            for (int b = 0; b < NBATCH; b++)
                #pragma unroll
                for (int j = 0; j < 4; j++)
                    xv[b][j] = __ldcg((const ulonglong2*)&g_hs3[cur_s][b * DD + lane * 4 + j * 128]);
        }

        unsigned long long acc2[3][NBATCH];
        #pragma unroll
        for (int g = 0; g < 3; g++)
            #pragma unroll
            for (int b = 0; b < NBATCH; b++) acc2[g][b] = 0ull;
        #pragma unroll
        for (int j = 0; j < 4; j++)
            #pragma unroll
            for (int g = 0; g < 3; g++)
                #pragma unroll
                for (int b = 0; b < NBATCH; b++) {
                    FMA2(acc2[g][b], wreg[g][j].x, xv[b][j].x, acc2[g][b]);
                    FMA2(acc2[g][b], wreg[g][j].y, xv[b][j].y, acc2[g][b]);
                }

        float a[3][NBATCH];
        #pragma unroll
        for (int g = 0; g < 3; g++)
            #pragma unroll
            for (int b = 0; b < NBATCH; b++) {
                float lo, hi;
                asm("mov.b64 {%0, %1}, %2;" : "=f"(lo), "=f"(hi) : "l"(acc2[g][b]));
                a[g][b] = lo + hi;
            }
        #pragma unroll
        for (int o = 16; o; o >>= 1)
            #pragma unroll
            for (int g = 0; g < 3; g++)
                #pragma unroll
                for (int b = 0; b < NBATCH; b++)
                    a[g][b] += __shfl_xor_sync(0xffffffffu, a[g][b], o);

        if (lane == 0) {
            #pragma unroll
            for (int g = 0; g < 3; g++)
                #pragma unroll
                for (int b = 0; b < NBATCH; b++)
                    sg[tr][g][b][il] = a[g][b];
        }
        __syncthreads();

        if (w == 0 && lane < 8 && t < TT) {         // fast GRU step t
            const int row = cb * TT + t;
            float r = sigf(gr + sg[0][0][cb][cil] + fb_r);
            float z = sigf(gz + sg[0][1][cb][cil] + fb_z);
            float n = tanhf_fast(gn + r * (sg[0][2][cb][cil] + fb_n));
            float hnew = (1.f - z) * n + z * hprev;
            g_hf3[nxt][cb * DD + ci] = hnew;
            pf[(size_t)row * DD + ci] = hnew;
            comb[(size_t)row * 2048 + ci] = hnew;
            if (t == TT - 1) hfT[cb * DD + ci] = hnew;
        }
        if (w == 1 && lane < 8 && t >= 1) {         // slow GRU step t-1
            const int ts = t - 1, row = cb * TT + ts;
            float r = sigf(sg[1][0][cb][cil] + sbi_r + sg[2][0][cb][cil] + sbh_r);
            float z = sigf(sg[1][1][cb][cil] + sbi_z + sg[2][1][cb][cil] + sbh_z);
            float n = tanhf_fast(sg[1][2][cb][cil] + sbi_n + r * (sg[2][2][cb][cil] + sbh_n));
            float hnew = (1.f - z) * n + z * hprev;
            g_hs3[nxt_s][cb * DD + ci] = hnew;
            ps[(size_t)row * DD + ci] = hnew;
            if (ts == TT - 1) hsT[cb * DD + ci] = hnew;
        }
        if (t < TT) grid_bar((unsigned)(t + 2));
    }
}

// ---------------- GEMM: 128x64 tile, 256 thr, 8x4/thread, f32x2 FMA ----------------
// TB=true : Bm stored [N,K]  (C = A @ Bm^T);  TB=false: Bm stored [K,N]
// CAUSAL: zero where col > row; fully-masked tiles skip the K loop.
// klim != 0: cap K at m0+128 (for S@v where S is lower-triangular).
// elu_cols: apply elu(x)+1 to output columns < elu_cols.
template <bool TB, bool CAUSAL>
__global__ void __launch_bounds__(256) gemm_kernel(
    const float* __restrict__ A, const float* __restrict__ Bm,
    const float* __restrict__ bias, float* __restrict__ C,
    int M, int N, int K, int lda, int ldb, int ldc,
    long long sA, long long sB, long long sC, float scale,
    int klim, int elu_cols)
{
    __shared__ __align__(16) float As[2][16][132];
    __shared__ __align__(16) float Bs[2][16][68];
    const int z = blockIdx.z;
    A += (size_t)z * sA; Bm += (size_t)z * sB; C += (size_t)z * sC;
    const int m0 = blockIdx.y * 128, n0 = blockIdx.x * 64;
    const int tid = threadIdx.x;
    const int ty = tid >> 4, tx = tid & 15;
    const int nn = n0 + (tx << 2);

    if (CAUSAL && n0 > m0 + 127) {      // fully-masked tile: just write zeros
        float4 zv = make_float4(0.f, 0.f, 0.f, 0.f);
        #pragma unroll
        for (int p2 = 0; p2 < 4; p2++)
            #pragma unroll
            for (int half = 0; half < 2; half++) {
                const int mm = m0 + (ty << 3) + (p2 << 1) + half;
                *(float4*)(C + (size_t)mm * ldc + nn) = zv;
            }
        return;
    }

    const int Kc = klim ? ((m0 + 128 < K) ? m0 + 128 : K) : K;
    const int ar = tid >> 2, ac = (tid & 3) << 2;
    const int bk = tid >> 4, bn = (tid & 15) << 2;

    float4 a0 = *(const float4*)(A + (size_t)(m0 + ar) * lda + ac);
    float4 a1 = *(const float4*)(A + (size_t)(m0 + ar + 64) * lda + ac);
    float4 bv;
    if (TB) bv = *(const float4*)(Bm + (size_t)(n0 + ar) * ldb + ac);
    else    bv = *(const float4*)(Bm + (size_t)bk * ldb + n0 + bn);

    {
        As[0][ac + 0][ar] = a0.x; As[0][ac + 1][ar] = a0.y;
        As[0][ac + 2][ar] = a0.z; As[0][ac + 3][ar] = a0.w;
        As[0][ac + 0][ar + 64] = a1.x; As[0][ac + 1][ar + 64] = a1.y;
        As[0][ac + 2][ar + 64] = a1.z; As[0][ac + 3][ar + 64] = a1.w;
        if (TB) {
            Bs[0][ac + 0][ar] = bv.x; Bs[0][ac + 1][ar] = bv.y;
            Bs[0][ac + 2][ar] = bv.z; Bs[0][ac + 3][ar] = bv.w;
        } else {
            *(float4*)&Bs[0][bk][bn] = bv;
        }
    }
    __syncthreads();

    unsigned long long acc[4][4];
    #pragma unroll
    for (int p2 = 0; p2 < 4; p2++)
        #pragma unroll
        for (int jj = 0; jj < 4; jj++) acc[p2][jj] = 0ull;

    const int P = Kc >> 4;
    int buf = 0;
    for (int p = 0; p < P; p++) {
        if (p + 1 < P) {
            const int k0n = (p + 1) << 4;
            a0 = *(const float4*)(A + (size_t)(m0 + ar) * lda + k0n + ac);
            a1 = *(const float4*)(A + (size_t)(m0 + ar + 64) * lda + k0n + ac);
            if (TB) bv = *(const float4*)(Bm + (size_t)(n0 + ar) * ldb + k0n + ac);
            else    bv = *(const float4*)(Bm + (size_t)(k0n + bk) * ldb + n0 + bn);
        }
        #pragma unroll
        for (int k = 0; k < 16; k++) {
            ulonglong2 alo = *(const ulonglong2*)&As[buf][k][ty << 3];
            ulonglong2 ahi = *(const ulonglong2*)&As[buf][k][(ty << 3) + 4];
            float4 b4 = *(const float4*)&Bs[buf][k][tx << 2];
            unsigned long long bd[4];
            asm("mov.b64 %0, {%1, %1};" : "=l"(bd[0]) : "f"(b4.x));
            asm("mov.b64 %0, {%1, %1};" : "=l"(bd[1]) : "f"(b4.y));
            asm("mov.b64 %0, {%1, %1};" : "=l"(bd[2]) : "f"(b4.z));
            asm("mov.b64 %0, {%1, %1};" : "=l"(bd[3]) : "f"(b4.w));
            #pragma unroll
            for (int jj = 0; jj < 4; jj++) {
                FMA2(acc[0][jj], alo.x, bd[jj], acc[0][jj]);
                FMA2(acc[1][jj], alo.y, bd[jj], acc[1][jj]);
                FMA2(acc[2][jj], ahi.x, bd[jj], acc[2][jj]);
                FMA2(acc[3][jj], ahi.y, bd[jj], acc[3][jj]);
            }
        }
        if (p + 1 < P) {
            const int nb = buf ^ 1;
            As[nb][ac + 0][ar] = a0.x; As[nb][ac + 1][ar] = a0.y;
            As[nb][ac + 2][ar] = a0.z; As[nb][ac + 3][ar] = a0.w;
            As[nb][ac + 0][ar + 64] = a1.x; As[nb][ac + 1][ar + 64] = a1.y;
            As[nb][ac + 2][ar + 64] = a1.z; As[nb][ac + 3][ar + 64] = a1.w;
            if (TB) {
                Bs[nb][ac + 0][ar] = bv.x; Bs[nb][ac + 1][ar] = bv.y;
                Bs[nb][ac + 2][ar] = bv.z; Bs[nb][ac + 3][ar] = bv.w;
            } else {
                *(float4*)&Bs[nb][bk][bn] = bv;
            }
            __syncthreads();
            buf = nb;
        }
    }

    float4 bvec;
    if (bias) bvec = *(const float4*)&bias[nn];
    #pragma unroll
    for (int p2 = 0; p2 < 4; p2++) {
        float rlo[4], rhi[4];
        #pragma unroll
        for (int jj = 0; jj < 4; jj++) {
            float lo, hi;
            asm("mov.b64 {%0, %1}, %2;" : "=f"(lo), "=f"(hi) : "l"(acc[p2][jj]));
            rlo[jj] = lo; rhi[jj] = hi;
        }
        #pragma unroll
        for (int half = 0; half < 2; half++) {
            const int mm = m0 + (ty << 3) + (p2 << 1) + half;
            float* rr = half ? rhi : rlo;
            float4 cv;
            cv.x = rr[0] * scale; cv.y = rr[1] * scale;
            cv.z = rr[2] * scale; cv.w = rr[3] * scale;
            if (bias) { cv.x += bvec.x; cv.y += bvec.y; cv.z += bvec.z; cv.w += bvec.w; }
            if (elu_cols) {
                if (nn + 0 < elu_cols) cv.x = cv.x > 0.f ? cv.x + 1.f : __expf(cv.x);
                if (nn + 1 < elu_cols) cv.y = cv.y > 0.f ? cv.y + 1.f : __expf(cv.y);
                if (nn + 2 < elu_cols) cv.z = cv.z > 0.f ? cv.z + 1.f : __expf(cv.z);
                if (nn + 3 < elu_cols) cv.w = cv.w > 0.f ? cv.w + 1.f : __expf(cv.w);
            }
            if (CAUSAL) {
                if (nn + 0 > mm) cv.x = 0.f;
                if (nn + 1 > mm) cv.y = 0.f;
                if (nn + 2 > mm) cv.z = 0.f;
                if (nn + 3 > mm) cv.w = 0.f;
            }
            *(float4*)(C + (size_t)mm * ldc + nn) = cv;
        }
    }
}

// ---------------- small kernels ----------------
// den = rowsum(S); l_mem (comb[:,1024:1536]) /= (den + 1e-6)  (fused)
__global__ void den_div_kernel() {
    __shared__ float sb[32];
    int row = blockIdx.x;
    float s = 0.f;
    for (int c = threadIdx.x; c < TT; c += 256) s += g_S[(size_t)row * TT + c];
    s = block_red_sum(s, sb);
    float inv = __fdividef(1.f, s + 1e-6f);
    for (int j = threadIdx.x; j < DD; j += 256)
        g_comb[(size_t)row * 2048 + 1024 + j] *= inv;
}

__global__ void softmax_kernel() {
    __shared__ float sb[32];
    int row = blockIdx.x;
    float x = g_attn[(size_t)row * MMEM + threadIdx.x];
    float m = block_red_max(x, sb);
    float e = __expf(x - m);
    float s = block_red_sum(e, sb);
    g_attn[(size_t)row * MMEM + threadIdx.x] = e / s;
}

__device__ __forceinline__ float tanh_bulk(float x) {
    float ax = fabsf(x);
    float t = __expf(-2.f * ax);
    float r = __fdividef(1.f - t, 1.f + t);
    return copysignf(r, x);
}

// mode 0: out = tanh(LN(in));  mode 1: out = LN(tanh(in))
__global__ void ln_kernel(const float* __restrict__ in, const float* __restrict__ gg,
                          const float* __restrict__ bb, float* __restrict__ out,
                          int ldo, int mode)
{
    __shared__ float sb[32];
    int row = blockIdx.x, tid = threadIdx.x;
    float x0 = in[(size_t)row * DD + tid];
    float x1 = in[(size_t)row * DD + 256 + tid];
    if (mode == 1) { x0 = tanh_bulk(x0); x1 = tanh_bulk(x1); }
    float s  = block_red_sum(x0 + x1, sb);
    float sq = block_red_sum(x0 * x0 + x1 * x1, sb);
    float mean = s * (1.f / 512.f);
    float var  = sq * (1.f / 512.f) - mean * mean;
    float rstd = rsqrtf(var + 1e-5f);
    float y0 = (x0 - mean) * rstd * gg[tid] + bb[tid];
    float y1 = (x1 - mean) * rstd * gg[256 + tid] + bb[256 + tid];
    if (mode == 0) { y0 = tanh_bulk(y0); y1 = tanh_bulk(y1); }
    out[(size_t)row * ldo + tid] = y0;
    out[(size_t)row * ldo + 256 + tid] = y1;
}

__global__ void rownorm_kernel(const float* __restrict__ src) {
    __shared__ float sb[32];
    int row = blockIdx.x, tid = threadIdx.x;
    float x0 = src[(size_t)row * DD + tid];
    float x1 = src[(size_t)row * DD + 256 + tid];
    float ss = block_red_sum(x0 * x0 + x1 * x1, sb);
    float inv = 1.f / fmaxf(sqrtf(ss), 1e-12f);
    g_sw[(size_t)row * DD + tid] = x0 * inv;
    g_sw[(size_t)row * DD + 256 + tid] = x1 * inv;
}

// ---------------- host ----------------
static inline void gemm(const float* A, const float* B, const float* bias, float* C,
                        int M, int N, int K, int lda, int ldb, int ldc,
                        float scale, int batch, long long sA, long long sB, long long sC,
                        bool tb, bool causal, int klim = 0, int elu_cols = 0)
{
    dim3 grid(N / 64, M / 128, batch);
    if (tb) {
        if (causal)
            gemm_kernel<true, true><<<grid, 256>>>(A, B, bias, C, M, N, K, lda, ldb, ldc, sA, sB, sC, scale, klim, elu_cols);
        else
            gemm_kernel<true, false><<<grid, 256>>>(A, B, bias, C, M, N, K, lda, ldb, ldc, sA, sB, sC, scale, klim, elu_cols);
    } else {
        gemm_kernel<false, false><<<grid, 256>>>(A, B, bias, C, M, N, K, lda, ldb, ldc, sA, sB, sC, scale, klim, elu_cols);
    }
}

extern "C" void kernel_launch(void* const* d_in, const int* in_sizes, int n_in,
                              void* d_out, int out_size)
{
    (void)in_sizes; (void)n_in; (void)out_size;
    const int*   x        = (const int*)d_in[0];
    const float* h_f      = (const float*)d_in[1];
    const float* h_s      = (const float*)d_in[2];
    const float* soma_w   = (const float*)d_in[3];
    const float* fast_wih = (const float*)d_in[4];
    const float* fast_whh = (const float*)d_in[5];
    const float* fast_bih = (const float*)d_in[6];
    const float* fast_bhh = (const float*)d_in[7];
    const float* slow_wih = (const float*)d_in[8];
    const float* slow_whh = (const float*)d_in[9];
    const float* slow_bih = (const float*)d_in[10];
    const float* slow_bhh = (const float*)d_in[11];
    const float* qkv_w    = (const float*)d_in[12];
    const float* qkv_b    = (const float*)d_in[13];
    const float* gate_w   = (const float*)d_in[14];
    const float* gate_b   = (const float*)d_in[15];
    const float* gate_g   = (const float*)d_in[16];
    const float* gate_bb  = (const float*)d_in[17];
    const float* mem_bank = (const float*)d_in[18];
    const float* hip_qw   = (const float*)d_in[19];
    const float* hip_qb   = (const float*)d_in[20];
    const float* axon_w   = (const float*)d_in[21];
    const float* axon_b   = (const float*)d_in[22];
    const float* norm_g   = (const float*)d_in[23];
    const float* norm_b   = (const float*)d_in[24];

    float* out = (float*)d_out;
    float* out_logits  = out;            // [B,T,V]
    float* out_thought = out + 262144;   // [B,T,D]
    float* out_hf      = out + 786432;   // [1,B,D]
    float* out_hs      = out + 787456;   // [1,B,D]

    float *p_table, *p_pf, *p_ps, *p_qkv, *p_S, *p_attn, *p_comb,
          *p_tpre, *p_gatepre, *p_qh, *p_sw;
    cudaGetSymbolAddress((void**)&p_table,   g_table);
    cudaGetSymbolAddress((void**)&p_pf,      g_pf);
    cudaGetSymbolAddress((void**)&p_ps,      g_ps);
    cudaGetSymbolAddress((void**)&p_qkv,     g_qkv);
    cudaGetSymbolAddress((void**)&p_S,       g_S);
    cudaGetSymbolAddress((void**)&p_attn,    g_attn);
    cudaGetSymbolAddress((void**)&p_comb,    g_comb);
    cudaGetSymbolAddress((void**)&p_tpre,    g_tpre);
    cudaGetSymbolAddress((void**)&p_gatepre, g_gatepre);
    cudaGetSymbolAddress((void**)&p_qh,      g_qh);
    cudaGetSymbolAddress((void**)&p_sw,      g_sw);

    // normalized embedding rows for logits
    rownorm_kernel<<<VV, 256>>>(soma_w);

    // fast-GRU input-gate token table: [V,3D] = soma_w @ fast_wih^T + fast_bih
    gemm(soma_w, fast_wih, fast_bih, p_table, 256, 1536, 512, 512, 512, 1536,
         1.f, 1, 0, 0, 0, true, false);

    // reset counter BEFORE the GRU (keeps fused_gru in the ncu window)
    reset_bar_kernel<<<1, 1>>>();

    // fused pipelined GRUs -> p_f, comb[:,0:512], p_s, hf1, hs1
    fused_gru_kernel<<<FUSE_BLOCKS, GRU_THREADS>>>(
        fast_whh, fast_bhh, slow_wih, slow_bih, slow_whh, slow_bhh,
        p_table, x, h_f, h_s, p_pf, p_comb, p_ps, out_hf, out_hs);

    // projections from p_s (elu fused into qkv epilogue for q,k cols)
    gemm(p_ps, qkv_w,  qkv_b,  p_qkv,     1024, 1536, 512, 512, 512, 1536, 1.f, 1, 0, 0, 0, true, false, 0, 1024);
    gemm(p_ps, gate_w, gate_b, p_gatepre, 1024,  512, 512, 512, 512,  512, 1.f, 1, 0, 0, 0, true, false);
    gemm(p_ps, hip_qw, hip_qb, p_qh,      1024,  512, 512, 512, 512,  512, 1.f, 1, 0, 0, 0, true, false);

    // linear attention == causal attention: S = q k^T (masked; masked tiles culled)
    gemm(p_qkv, p_qkv + 512, nullptr, p_S, 512, 512, 512, 1536, 1536, 512,
         1.f, 2, 512LL * 1536, 512LL * 1536, 512LL * 512, true, true);
    // num = S @ v -> combined[:, 1024:1536]  (K capped at m0+128: S upper is zero)
    gemm(p_S, p_qkv + 1024, nullptr, p_comb + 1024, 512, 512, 512, 512, 1536, 2048,
         1.f, 2, 512LL * 512, 512LL * 1536, 512LL * 2048, false, false, 1, 0);
    // den + divide fused
    den_div_kernel<<<BT, 256>>>();

    // intent = tanh(LN(gatepre)) -> combined[:, 512:1024]
    ln_kernel<<<BT, 256>>>(p_gatepre, gate_g, gate_bb, p_comb + 512, 2048, 0);

    // hippocampus: attn = softmax(qh @ mem^T / sqrt(D)); episodes = attn @ mem
    gemm(p_qh, mem_bank, nullptr, p_attn, 1024, 256, 512, 512, 512, 256,
         0.044194173824159216f, 1, 0, 0, 0, true, false);
    softmax_kernel<<<BT, 256>>>();
    gemm(p_attn, mem_bank, nullptr, p_comb + 1536, 1024, 512, 256, 256, 512, 2048,
         1.f, 1, 0, 0, 0, false, false);

    // thought = LN(tanh(combined @ axon_w^T + axon_b))
    gemm(p_comb, axon_w, axon_b, p_tpre, 1024, 512, 2048, 2048, 2048, 512,
         1.f, 1, 0, 0, 0, true, false);
    ln_kernel<<<BT, 256>>>(p_tpre, norm_g, norm_b, out_thought, 512, 1);

    // logits = (thought @ sw^T) * 16
    gemm(out_thought, p_sw, nullptr, out_logits, 1024, 256, 512, 512, 512, 256,
         16.f, 1, 0, 0, 0, true, false);
}